// round 3
// baseline (speedup 1.0000x reference)
#include <cuda_runtime.h>
#include <cstdint>
#include <cstddef>

#define HS 64
#define SROWS 66  // 2 + HEAD_SIZE

// tanh activations scratch: [B*S, 160] fp32
__device__ float g_act[8192 * 160];

// ---------------------------------------------------------------------------
// Kernel A: GEMM1 + tanh.  act[M,160] = tanh( XM[M,D] @ W1[D,160] )
// XM computed on the fly: xm = x + (prev - x) * tmx, prev = x[t-1] or state row.
// Tile: M=64, N=160 (full), K-tile=32. 256 threads as 16x16, 4x10 acc/thread.
// ---------------------------------------------------------------------------
__global__ __launch_bounds__(256) void k_gemm1(
    const float* __restrict__ x, const float* __restrict__ state,
    const float* __restrict__ tmx, const float* __restrict__ w1,
    const int* __restrict__ ip, int B, int S, int D)
{
    __shared__ float xs[64 * 36];     // [row][k], stride 36 (16B-aligned pad)
    __shared__ float ws[32 * 160];    // [k][col]

    const int tid = threadIdx.x;
    const int tx = tid & 15, ty = tid >> 4;
    const int mbase = blockIdx.x * 64;
    const int i1 = SROWS * ip[0] + 1;

    // Precompute per-thread loader pointers (fixed across K-tiles).
    const float* xp[2];
    const float* pp[2];
    const float* tp[2];
    float* sp[2];
#pragma unroll
    for (int it = 0; it < 2; it++) {
        int e  = tid + it * 256;        // float4 slot: 512 total = 64 rows x 8
        int r  = e >> 3;
        int c  = (e & 7) * 4;
        int m  = mbase + r;
        int b  = m / S;
        int s  = m - b * S;
        xp[it] = x + (size_t)m * D + c;
        pp[it] = (s == 0) ? (state + ((size_t)b * SROWS + i1) * D + c)
                          : (x + (size_t)(m - 1) * D + c);
        tp[it] = tmx + c;
        sp[it] = xs + r * 36 + c;
    }

    float acc[4][10];
#pragma unroll
    for (int i = 0; i < 4; i++)
#pragma unroll
        for (int j = 0; j < 10; j++) acc[i][j] = 0.f;

    const int KT = D >> 5;  // 64
    for (int kt = 0; kt < KT; kt++) {
        const int kbase = kt << 5;
        // ---- load XM tile (compute mixing on the fly) ----
#pragma unroll
        for (int it = 0; it < 2; it++) {
            float4 xv = *(const float4*)(xp[it] + kbase);
            float4 pv = *(const float4*)(pp[it] + kbase);
            float4 tv = *(const float4*)(tp[it] + kbase);
            float4 o;
            o.x = fmaf(pv.x - xv.x, tv.x, xv.x);
            o.y = fmaf(pv.y - xv.y, tv.y, xv.y);
            o.z = fmaf(pv.z - xv.z, tv.z, xv.z);
            o.w = fmaf(pv.w - xv.w, tv.w, xv.w);
            *(float4*)(sp[it]) = o;
        }
        // ---- load W1 tile: rows kbase..kbase+31 are CONTIGUOUS in gmem ----
        {
            const float4* wsrc = (const float4*)(w1 + (size_t)kbase * 160);
            float4* wdst = (float4*)ws;
#pragma unroll
            for (int it = 0; it < 5; it++)
                wdst[tid + it * 256] = wsrc[tid + it * 256];
        }
        __syncthreads();
#pragma unroll 8
        for (int k = 0; k < 32; k++) {
            float a[4], bb[10];
#pragma unroll
            for (int i = 0; i < 4; i++) a[i] = xs[(ty * 4 + i) * 36 + k];
#pragma unroll
            for (int j = 0; j < 10; j++) bb[j] = ws[k * 160 + tx * 10 + j];
#pragma unroll
            for (int i = 0; i < 4; i++)
#pragma unroll
                for (int j = 0; j < 10; j++)
                    acc[i][j] = fmaf(a[i], bb[j], acc[i][j]);
        }
        __syncthreads();
    }

#pragma unroll
    for (int i = 0; i < 4; i++) {
        int m = mbase + ty * 4 + i;
#pragma unroll
        for (int j = 0; j < 10; j++)
            g_act[(size_t)m * 160 + tx * 10 + j] = tanhf(acc[i][j]);
    }
}

// ---------------------------------------------------------------------------
// Kernel B: GEMM2 (K=32, block-diagonal over f) + full epilogue.
// out[m,f,d] = x[m,d] + sx[m,d] * (stacked[f,d] + sum_k act[m,f*32+k]*W2[f,k,d])
// Block tile: 32 tokens x 128 d-cols, one f. 256 threads: tx 0..31 (4 d each,
// float4), ty 0..7 (4 tokens each). 16 acc/thread.
// ---------------------------------------------------------------------------
__global__ __launch_bounds__(256) void k_gemm2(
    const float* __restrict__ x, const float* __restrict__ state,
    const float* __restrict__ w2,
    const float* __restrict__ mk, const float* __restrict__ mw,
    const float* __restrict__ mv, const float* __restrict__ mr,
    const float* __restrict__ mg,
    const int* __restrict__ ip,
    float* __restrict__ out, int B, int S, int D)
{
    __shared__ float As[32 * 32];    // [token][k]  (broadcast reads, no pad needed)
    __shared__ float Ws[32 * 128];   // [k][d]

    const int tid = threadIdx.x;
    const int tx = tid & 31, ty = tid >> 5;
    const int dbase = blockIdx.x * 128;
    const int f = blockIdx.y;
    const int mbase = blockIdx.z * 32;
    const int i1 = SROWS * ip[0] + 1;

    // load As: 1024 floats = 256 float4 (act rows: 32 contiguous floats each)
    {
        int r = tid >> 3, c = (tid & 7) * 4;
        *(float4*)(As + r * 32 + c) =
            *(const float4*)(g_act + (size_t)(mbase + r) * 160 + f * 32 + c);
    }
    // load Ws: 32 rows x 128 cols from W2[f]
    {
        const float* wsrc = w2 + (size_t)f * 32 * D + dbase;
#pragma unroll
        for (int it = 0; it < 4; it++) {
            int e = tid + it * 256;
            int r = e >> 5, c = (e & 31) * 4;
            *(float4*)(Ws + r * 128 + c) = *(const float4*)(wsrc + (size_t)r * D + c);
        }
    }
    __syncthreads();

    float acc[4][4];
#pragma unroll
    for (int i = 0; i < 4; i++)
#pragma unroll
        for (int j = 0; j < 4; j++) acc[i][j] = 0.f;

#pragma unroll 8
    for (int k = 0; k < 32; k++) {
        float4 w = *(const float4*)(Ws + k * 128 + tx * 4);
#pragma unroll
        for (int i = 0; i < 4; i++) {
            float a = As[(ty * 4 + i) * 32 + k];
            acc[i][0] = fmaf(a, w.x, acc[i][0]);
            acc[i][1] = fmaf(a, w.y, acc[i][1]);
            acc[i][2] = fmaf(a, w.z, acc[i][2]);
            acc[i][3] = fmaf(a, w.w, acc[i][3]);
        }
    }

    const float* st = (f == 0) ? mk : (f == 1) ? mw : (f == 2) ? mv
                    : (f == 3) ? mr : mg;
    const int d = dbase + tx * 4;
    const float4 stv = *(const float4*)(st + d);

#pragma unroll
    for (int i = 0; i < 4; i++) {
        int m = mbase + ty * 4 + i;
        int b = m / S;
        int s = m - b * S;
        float4 xv = *(const float4*)(x + (size_t)m * D + d);
        float4 pv = (s == 0)
            ? *(const float4*)(state + ((size_t)b * SROWS + i1) * D + d)
            : *(const float4*)(x + (size_t)(m - 1) * D + d);
        float4 o;
        o.x = fmaf(pv.x - xv.x, stv.x + acc[i][0], xv.x);
        o.y = fmaf(pv.y - xv.y, stv.y + acc[i][1], xv.y);
        o.z = fmaf(pv.z - xv.z, stv.z + acc[i][2], xv.z);
        o.w = fmaf(pv.w - xv.w, stv.w + acc[i][3], xv.w);
        *(float4*)(out + ((size_t)m * 5 + f) * D + d) = o;
    }
}

// ---------------------------------------------------------------------------
// Kernel C: new_state = state with row i1 <- x[:, S-1, :]
// ---------------------------------------------------------------------------
__global__ void k_state(
    const float* __restrict__ x, const float* __restrict__ state,
    const int* __restrict__ ip, float* __restrict__ outs,
    int B, int S, int D)
{
    int idx = blockIdx.x * blockDim.x + threadIdx.x;
    int n = B * SROWS * D;
    if (idx >= n) return;
    int i1 = SROWS * ip[0] + 1;
    int d = idx % D;
    int r = (idx / D) % SROWS;
    int b = idx / (D * SROWS);
    float v = (r == i1) ? x[((size_t)b * S + (S - 1)) * D + d] : state[idx];
    outs[idx] = v;
}

extern "C" void kernel_launch(void* const* d_in, const int* in_sizes, int n_in,
                              void* d_out, int out_size)
{
    const float* x     = (const float*)d_in[0];
    const float* state = (const float*)d_in[1];
    const float* tmx   = (const float*)d_in[2];
    const float* w1    = (const float*)d_in[3];
    const float* w2    = (const float*)d_in[4];
    const float* mk    = (const float*)d_in[5];
    const float* mw    = (const float*)d_in[6];
    const float* mv    = (const float*)d_in[7];
    const float* mr    = (const float*)d_in[8];
    const float* mg    = (const float*)d_in[9];
    const int*   ip    = (const int*)d_in[10];

    const int D = in_sizes[2];
    const int B = in_sizes[1] / (SROWS * D);
    const int S = in_sizes[0] / (B * D);
    const int M = B * S;

    float* out  = (float*)d_out;
    float* outs = out + (size_t)M * 5 * D;

    k_gemm1<<<M / 64, 256>>>(x, state, tmx, w1, ip, B, S, D);

    dim3 g2(D / 128, 5, M / 32);
    k_gemm2<<<g2, 256>>>(x, state, w2, mk, mw, mv, mr, mg, ip, out, B, S, D);

    // Only write the state tail if the harness allocated room for it.
    size_t main_elems = (size_t)M * 5 * D;
    size_t state_elems = (size_t)B * SROWS * D;
    if ((size_t)out_size >= main_elems + state_elems) {
        int n = B * SROWS * D;
        k_state<<<(n + 255) / 256, 256>>>(x, state, ip, outs, B, S, D);
    }
}

// round 6
// speedup vs baseline: 1.3359x; 1.3359x over previous
#include <cuda_runtime.h>
#include <cstdint>
#include <cstddef>

#define SROWS 66  // 2 + HEAD_SIZE

// scratch
__device__ float g_act[8192 * 160];            // tanh activations fp32
__device__ __align__(16) float g_w1cv[2048 * 160];  // W1 pre-rounded to tf32, [K,160]

__device__ __forceinline__ uint32_t f2tf32(float f) {
    uint32_t u;
    asm("cvt.rna.tf32.f32 %0, %1;" : "=r"(u) : "f"(f));
    return u;
}

// ---------------------------------------------------------------------------
// Kernel T: round W1 to tf32 (keeps [K,160] layout == .col B-fragment layout)
// ---------------------------------------------------------------------------
__global__ void k_w1cv(const float* __restrict__ w1, int n)
{
    int idx = blockIdx.x * blockDim.x + threadIdx.x;
    if (idx >= n) return;
    uint32_t u = f2tf32(w1[idx]);
    g_w1cv[idx] = __uint_as_float(u);
}

// ---------------------------------------------------------------------------
// Kernel A (mma.sync tf32): act[M,160] = tanh( XM[M,2048] @ W1[2048,160] )
// XM computed on the fly: xm = x + (prev - x) * tmx.
// Block: 256 thr (8 warps), tile M=64 x N=160. Warp: 4m x 2n grid,
// warp tile m16 x n80 (10 n-tiles of m16n8k8). K chunks of 32 (4 k-steps).
// ---------------------------------------------------------------------------
__global__ __launch_bounds__(256) void k_gemm1_mma(
    const float* __restrict__ x, const float* __restrict__ state,
    const float* __restrict__ tmx, const int* __restrict__ ip,
    int B, int S, int D)
{
    __shared__ uint32_t As[64 * 36];    // [m][k] tf32 bits, stride 36 (conflict-free frags)
    __shared__ uint32_t Bs[32 * 168];   // [k][n] tf32 bits, stride 168

    const int tid = threadIdx.x;
    const int wid = tid >> 5, lane = tid & 31;
    const int g = lane >> 2, t = lane & 3;      // group / thread-in-group
    const int warp_m = wid & 3, warp_n = wid >> 2;
    const int mbase = blockIdx.x * 64;
    const int i1 = SROWS * ip[0] + 1;

    // ---- A-tile loader addressing (fixed across chunks) ----
    // 64 rows x 32 cols = 512 float4 slots; 2 per thread.
    const int cg = tid & 7;                  // col group (4 floats)
    const float* xrow[2];
    const float* prow[2];
    uint32_t* adst[2];
#pragma unroll
    for (int it = 0; it < 2; it++) {
        int r = (tid >> 3) + 32 * it;
        int m = mbase + r;
        int b = m / S;
        int s = m - b * S;
        xrow[it] = x + (size_t)m * D + cg * 4;
        prow[it] = (s == 0) ? (state + ((size_t)b * SROWS + i1) * D + cg * 4)
                            : (x + (size_t)(m - 1) * D + cg * 4);
        adst[it] = As + r * 36 + cg * 4;
    }
    // B-tile loader: 32 rows x 160 cols = 1280 float4 slots; 5 per thread.
    int brow[5], bcol[5];
#pragma unroll
    for (int it = 0; it < 5; it++) {
        int e = tid + it * 256;
        brow[it] = e / 40;
        bcol[it] = (e - brow[it] * 40) * 4;
    }

    float acc[10][4];
#pragma unroll
    for (int nt = 0; nt < 10; nt++)
#pragma unroll
        for (int j = 0; j < 4; j++) acc[nt][j] = 0.f;

    const int KT = D >> 5;  // 64 chunks of 32
    for (int kt = 0; kt < KT; kt++) {
        const int kbase = kt << 5;
        // ---- fill A: mixing + tf32 round ----
#pragma unroll
        for (int it = 0; it < 2; it++) {
            float4 xv = *(const float4*)(xrow[it] + kbase);
            float4 pv = *(const float4*)(prow[it] + kbase);
            float4 tv = *(const float4*)(tmx + kbase + cg * 4);
            uint4 o;
            o.x = f2tf32(fmaf(pv.x - xv.x, tv.x, xv.x));
            o.y = f2tf32(fmaf(pv.y - xv.y, tv.y, xv.y));
            o.z = f2tf32(fmaf(pv.z - xv.z, tv.z, xv.z));
            o.w = f2tf32(fmaf(pv.w - xv.w, tv.w, xv.w));
            *(uint4*)(adst[it]) = o;
        }
        // ---- fill B: copy pre-rounded W1 rows (contiguous in gmem) ----
        {
            const float* wsrc = g_w1cv + (size_t)kbase * 160;
#pragma unroll
            for (int it = 0; it < 5; it++) {
                *(uint4*)(Bs + brow[it] * 168 + bcol[it]) =
                    *(const uint4*)(wsrc + (size_t)brow[it] * 160 + bcol[it]);
            }
        }
        __syncthreads();

#pragma unroll
        for (int ks = 0; ks < 4; ks++) {
            const int k0 = ks * 8;
            // A fragment (one m16 tile per warp)
            const int ar = warp_m * 16 + g;
            uint32_t a0 = As[ar * 36 + k0 + t];
            uint32_t a1 = As[(ar + 8) * 36 + k0 + t];
            uint32_t a2 = As[ar * 36 + k0 + t + 4];
            uint32_t a3 = As[(ar + 8) * 36 + k0 + t + 4];
#pragma unroll
            for (int nt = 0; nt < 10; nt++) {
                const int nc = warp_n * 80 + nt * 8 + g;
                uint32_t b0 = Bs[(k0 + t) * 168 + nc];
                uint32_t b1 = Bs[(k0 + t + 4) * 168 + nc];
                asm volatile(
                    "mma.sync.aligned.m16n8k8.row.col.f32.tf32.tf32.f32 "
                    "{%0,%1,%2,%3}, {%4,%5,%6,%7}, {%8,%9}, {%0,%1,%2,%3};"
                    : "+f"(acc[nt][0]), "+f"(acc[nt][1]),
                      "+f"(acc[nt][2]), "+f"(acc[nt][3])
                    : "r"(a0), "r"(a1), "r"(a2), "r"(a3), "r"(b0), "r"(b1));
            }
        }
        __syncthreads();
    }

    // ---- epilogue: tanh -> g_act ----
    const int m0 = mbase + warp_m * 16 + g;
#pragma unroll
    for (int nt = 0; nt < 10; nt++) {
        const int n = warp_n * 80 + nt * 8 + t * 2;
        float2 lo = make_float2(tanhf(acc[nt][0]), tanhf(acc[nt][1]));
        float2 hi = make_float2(tanhf(acc[nt][2]), tanhf(acc[nt][3]));
        *(float2*)(g_act + (size_t)m0 * 160 + n) = lo;
        *(float2*)(g_act + (size_t)(m0 + 8) * 160 + n) = hi;
    }
}

// ---------------------------------------------------------------------------
// Kernel B: GEMM2 (K=32 per f) + epilogue, all 5 f fused per block.
// Tile: 32 tokens x 128 d. x/prev loaded once into regs, reused across f.
// ---------------------------------------------------------------------------
__global__ __launch_bounds__(256) void k_gemm2(
    const float* __restrict__ x, const float* __restrict__ state,
    const float* __restrict__ w2,
    const float* __restrict__ mk, const float* __restrict__ mw,
    const float* __restrict__ mv, const float* __restrict__ mr,
    const float* __restrict__ mg,
    const int* __restrict__ ip,
    float* __restrict__ out, int B, int S, int D)
{
    __shared__ float As[32 * 160];   // act tile, all 5 f
    __shared__ float Ws[32 * 128];   // current f's weight tile

    const int tid = threadIdx.x;
    const int tx = tid & 31, ty = tid >> 5;
    const int dbase = blockIdx.x * 128;
    const int mbase = blockIdx.y * 32;
    const int i1 = SROWS * ip[0] + 1;

    // load As: 5120 floats = 1280 float4
#pragma unroll
    for (int it = 0; it < 5; it++) {
        int e = tid + it * 256;
        int r = e / 40, c = (e - r * 40) * 4;
        *(float4*)(As + r * 160 + c) =
            *(const float4*)(g_act + (size_t)(mbase + r) * 160 + c);
    }

    // preload x/prev for this thread's 4 tokens (reused across all 5 f)
    const int d = dbase + tx * 4;
    float4 xv[4], pv[4];
#pragma unroll
    for (int i = 0; i < 4; i++) {
        int m = mbase + ty * 4 + i;
        int b = m / S;
        int s = m - b * S;
        xv[i] = *(const float4*)(x + (size_t)m * D + d);
        pv[i] = (s == 0)
            ? *(const float4*)(state + ((size_t)b * SROWS + i1) * D + d)
            : *(const float4*)(x + (size_t)(m - 1) * D + d);
    }
    __syncthreads();

    for (int f = 0; f < 5; f++) {
        if (f) __syncthreads();   // previous Ws fully consumed
        // load Ws[f]: 32 rows x 128 cols
#pragma unroll
        for (int it = 0; it < 4; it++) {
            int e = tid + it * 256;
            int r = e >> 5, c = (e & 31) * 4;
            *(float4*)(Ws + r * 128 + c) =
                *(const float4*)(w2 + ((size_t)f * 32 + r) * D + dbase + c);
        }
        __syncthreads();

        float acc[4][4];
#pragma unroll
        for (int i = 0; i < 4; i++)
#pragma unroll
            for (int j = 0; j < 4; j++) acc[i][j] = 0.f;

#pragma unroll 8
        for (int k = 0; k < 32; k++) {
            float4 w = *(const float4*)(Ws + k * 128 + tx * 4);
#pragma unroll
            for (int i = 0; i < 4; i++) {
                float a = As[(ty * 4 + i) * 160 + f * 32 + k];
                acc[i][0] = fmaf(a, w.x, acc[i][0]);
                acc[i][1] = fmaf(a, w.y, acc[i][1]);
                acc[i][2] = fmaf(a, w.z, acc[i][2]);
                acc[i][3] = fmaf(a, w.w, acc[i][3]);
            }
        }

        const float* st = (f == 0) ? mk : (f == 1) ? mw : (f == 2) ? mv
                        : (f == 3) ? mr : mg;
        const float4 stv = *(const float4*)(st + d);
#pragma unroll
        for (int i = 0; i < 4; i++) {
            int m = mbase + ty * 4 + i;
            float4 o;
            o.x = fmaf(pv[i].x - xv[i].x, stv.x + acc[i][0], xv[i].x);
            o.y = fmaf(pv[i].y - xv[i].y, stv.y + acc[i][1], xv[i].y);
            o.z = fmaf(pv[i].z - xv[i].z, stv.z + acc[i][2], xv[i].z);
            o.w = fmaf(pv[i].w - xv[i].w, stv.w + acc[i][3], xv[i].w);
            *(float4*)(out + ((size_t)m * 5 + f) * D + d) = o;
        }
    }
}

// ---------------------------------------------------------------------------
// Kernel C: new_state = state with row i1 <- x[:, S-1, :]
// ---------------------------------------------------------------------------
__global__ void k_state(
    const float* __restrict__ x, const float* __restrict__ state,
    const int* __restrict__ ip, float* __restrict__ outs,
    int B, int S, int D)
{
    int idx = blockIdx.x * blockDim.x + threadIdx.x;
    int n = B * SROWS * D;
    if (idx >= n) return;
    int i1 = SROWS * ip[0] + 1;
    int d = idx % D;
    int r = (idx / D) % SROWS;
    int b = idx / (D * SROWS);
    float v = (r == i1) ? x[((size_t)b * S + (S - 1)) * D + d] : state[idx];
    outs[idx] = v;
}

extern "C" void kernel_launch(void* const* d_in, const int* in_sizes, int n_in,
                              void* d_out, int out_size)
{
    const float* x     = (const float*)d_in[0];
    const float* state = (const float*)d_in[1];
    const float* tmx   = (const float*)d_in[2];
    const float* w1    = (const float*)d_in[3];
    const float* w2    = (const float*)d_in[4];
    const float* mk    = (const float*)d_in[5];
    const float* mw    = (const float*)d_in[6];
    const float* mv    = (const float*)d_in[7];
    const float* mr    = (const float*)d_in[8];
    const float* mg    = (const float*)d_in[9];
    const int*   ip    = (const int*)d_in[10];

    const int D = in_sizes[2];
    const int B = in_sizes[1] / (SROWS * D);
    const int S = in_sizes[0] / (B * D);
    const int M = B * S;

    float* out  = (float*)d_out;
    float* outs = out + (size_t)M * 5 * D;

    k_w1cv<<<(160 * D + 255) / 256, 256>>>(w1, 160 * D);
    k_gemm1_mma<<<M / 64, 256>>>(x, state, tmx, ip, B, S, D);

    dim3 g2(D / 128, M / 32);
    k_gemm2<<<g2, 256>>>(x, state, w2, mk, mw, mv, mr, mg, ip, out, B, S, D);

    size_t main_elems  = (size_t)M * 5 * D;
    size_t state_elems = (size_t)B * SROWS * D;
    if ((size_t)out_size >= main_elems + state_elems) {
        int n = B * SROWS * D;
        k_state<<<(n + 255) / 256, 256>>>(x, state, ip, outs, B, S, D);
    }
}